// round 14
// baseline (speedup 1.0000x reference)
#include <cuda_runtime.h>
#include <cuda_bf16.h>
#include <cstdint>

#define Dq 128          // feature dim (fixed by problem)
#define MAXN 40960
#define MAXE 665600
#define SCAN_BLK 1024
#define MAX_SCAN_BLOCKS ((MAXN + SCAN_BLK - 1) / SCAN_BLK)

// ---- static device scratch (allocation-free rule) ----
// z/zi/asrc/adst are double-buffered by layer parity: layer l's aggregate
// reads bank l&1 while layer l+1's GEMM concurrently writes bank (l+1)&1.
__device__ float g_zb [2][MAXN * Dq];
__device__ float g_zib[2][MAXN * Dq];
__device__ float g_asb[2][MAXN];
__device__ float g_adb[2][MAXN];
__device__ float g_hA[MAXN * Dq];   // layer ping
__device__ float g_hB[MAXN * Dq];   // layer pong
__device__ int   g_deg[MAXN];
__device__ int   g_excl[MAXN];      // per-chunk exclusive scan (no block offset)
__device__ int   g_btot[MAX_SCAN_BLOCKS];
__device__ int   g_boff[MAX_SCAN_BLOCKS + 1];
__device__ int   g_rowptr[MAXN + 1];
__device__ int   g_cursor[MAXN];
__device__ uint2 g_edge[MAXE];      // CSR (by dst): {src, d-bits} packed
__device__ uint32_t g_Wpack[3 * 4 * 8192];  // per layer: B1h,B1l,B2h,B2l [n=128][kp=64]

// pack two floats as bf16x2 (lo k in low 16 bits)
__device__ __forceinline__ uint32_t packbf(float a, float b) {
    unsigned short ua = __bfloat16_as_ushort(__float2bfloat16_rn(a));
    unsigned short ub = __bfloat16_as_ushort(__float2bfloat16_rn(b));
    return ((uint32_t)ub << 16) | (uint32_t)ua;
}

// m16n8k16 bf16 MMA, fp32 accumulate in place
__device__ __forceinline__ void mma16(float* c, const uint32_t* a,
                                      uint32_t b0, uint32_t b1) {
    asm volatile("mma.sync.aligned.m16n8k16.row.col.f32.bf16.bf16.f32 "
                 "{%0,%1,%2,%3}, {%4,%5,%6,%7}, {%8,%9}, {%0,%1,%2,%3};"
                 : "+f"(c[0]), "+f"(c[1]), "+f"(c[2]), "+f"(c[3])
                 : "r"(a[0]), "r"(a[1]), "r"(a[2]), "r"(a[3]),
                   "r"(b0), "r"(b1));
}

// ------------------------------------------------------------------
// W packing: all L layers, W1/W2 -> n-major bf16 hi/lo k-pair tiles
// ------------------------------------------------------------------
__global__ void k_packW(const float* __restrict__ W1,
                        const float* __restrict__ W2, int L) {
    int idx = blockIdx.x * blockDim.x + threadIdx.x;
    int total = L * 2 * 8192;
    if (idx >= total) return;
    int l = idx / 16384;
    int r = idx - l * 16384;
    int m = r >> 13;               // 0 = W1, 1 = W2
    int rr = r & 8191;
    int kp = rr >> 7;              // 0..63
    int n = rr & 127;
    const float* W = (m ? W2 : W1) + (size_t)l * Dq * Dq;
    float x0 = W[(2 * kp) * 128 + n];
    float x1 = W[(2 * kp + 1) * 128 + n];
    __nv_bfloat16 b0 = __float2bfloat16_rn(x0);
    __nv_bfloat16 b1 = __float2bfloat16_rn(x1);
    uint32_t hi = ((uint32_t)__bfloat16_as_ushort(b1) << 16)
                |  (uint32_t)__bfloat16_as_ushort(b0);
    uint32_t lo = packbf(x0 - __bfloat162float(b0), x1 - __bfloat162float(b1));
    uint32_t* base = g_Wpack + (size_t)l * 4 * 8192;
    base[(2 * m + 0) * 8192 + n * 64 + kp] = hi;
    base[(2 * m + 1) * 8192 + n * 64 + kp] = lo;
}

// ------------------------------------------------------------------
// CSR build
// ------------------------------------------------------------------
__global__ void k_zero_deg(int N) {
    int i = blockIdx.x * blockDim.x + threadIdx.x;
    if (i < N) g_deg[i] = 0;
}

__global__ void k_hist(const int* __restrict__ dst, int E) {
    int e = blockIdx.x * blockDim.x + threadIdx.x;
    if (e < E) atomicAdd(&g_deg[dst[e]], 1);
}

// phase 1: per-block exclusive scan of a 1024 chunk + block total
__global__ void k_scan1(int N) {
    __shared__ int wtot[32];
    int tid = threadIdx.x, lane = tid & 31, wid = tid >> 5;
    int i = blockIdx.x * SCAN_BLK + tid;
    int v = (i < N) ? g_deg[i] : 0;
    int x = v;
#pragma unroll
    for (int o = 1; o < 32; o <<= 1) {
        int t = __shfl_up_sync(0xffffffffu, x, o);
        if (lane >= o) x += t;
    }
    if (lane == 31) wtot[wid] = x;
    __syncthreads();
    if (wid == 0) {
        int w = wtot[lane];
#pragma unroll
        for (int o = 1; o < 32; o <<= 1) {
            int t = __shfl_up_sync(0xffffffffu, w, o);
            if (lane >= o) w += t;
        }
        wtot[lane] = w;
    }
    __syncthreads();
    int pre = (wid > 0 ? wtot[wid - 1] : 0);
    if (i < N) g_excl[i] = pre + x - v;
    if (tid == SCAN_BLK - 1) g_btot[blockIdx.x] = pre + x;
}

// phase 2: scan the block totals (tiny)
__global__ void k_scan2(int nblocks) {
    int lane = threadIdx.x & 31, wid = threadIdx.x >> 5;
    __shared__ int wtot[32];
    int i = threadIdx.x;
    int v = (i < nblocks) ? g_btot[i] : 0;
    int x = v;
#pragma unroll
    for (int o = 1; o < 32; o <<= 1) {
        int t = __shfl_up_sync(0xffffffffu, x, o);
        if (lane >= o) x += t;
    }
    if (lane == 31) wtot[wid] = x;
    __syncthreads();
    if (wid == 0) {
        int w = (lane < 2) ? wtot[lane] : 0;   // <= 64 threads used
#pragma unroll
        for (int o = 1; o < 32; o <<= 1) {
            int t = __shfl_up_sync(0xffffffffu, w, o);
            if (lane >= o) w += t;
        }
        wtot[lane] = w;
    }
    __syncthreads();
    int pre = (wid > 0 ? wtot[wid - 1] : 0);
    if (i <= nblocks) g_boff[i] = pre + x - v;   // exclusive; g_boff[nblocks]=total
    if (i == nblocks) g_boff[i] = pre + x - v;
}

// phase 3: add block offsets, emit rowptr + cursor
__global__ void k_scan3(int N, int nblocks) {
    int i = blockIdx.x * SCAN_BLK + threadIdx.x;
    if (i < N) {
        int r = g_excl[i] + g_boff[blockIdx.x];
        g_rowptr[i] = r;
        g_cursor[i] = r;
    }
    if (i == 0) g_rowptr[N] = g_boff[nblocks];
}

__global__ void k_scatter(const int* __restrict__ src, const int* __restrict__ dst,
                          const float* __restrict__ dval, int E) {
    int e = blockIdx.x * blockDim.x + threadIdx.x;
    if (e < E) {
        int p = atomicAdd(&g_cursor[dst[e]], 1);
        g_edge[p] = make_uint2((uint32_t)src[e], __float_as_uint(dval[e]));
    }
}

// ------------------------------------------------------------------
// Tensor-core GEMM via mma.sync m16n8k16 bf16 (3-term hi/lo split):
//   zout = h@W1, ziout = h@W2. Block: 128 rows x 128 cols, K=128 in smem.
// row0: first row of this launch's range. Outputs go to the given bank.
// ------------------------------------------------------------------
#define SP 68                           // row stride in u32 (64 k-pairs + 4 pad)
#define TILE_U32 8704                   // 128 * 68
#define DYN_SMEM (52224 * 4)            // 208896 bytes

__global__ __launch_bounds__(256, 1)
void k_gemm_mma(const float* __restrict__ h,
                const uint32_t* __restrict__ wpack,
                const float* __restrict__ Wal,
                int N, int row0,
                float* __restrict__ zout, float* __restrict__ ziout,
                float* __restrict__ asout, float* __restrict__ adout) {
    extern __shared__ uint32_t dsu[];
    __shared__ float s_wa[256];

    uint32_t* A_hi = dsu;
    uint32_t* A_lo = dsu + TILE_U32;
    uint32_t* Bb   = dsu + 2 * TILE_U32;   // 4 tiles: B1h,B1l,B2h,B2l

    int tid = threadIdx.x, wid = tid >> 5, lane = tid & 31;
    int g = lane >> 2, tg = lane & 3;
    int rb = row0 + blockIdx.x * 128;

    s_wa[tid] = Wal[tid];

    float acc1[16][4], acc2[16][4];
#pragma unroll
    for (int nt = 0; nt < 16; ++nt)
#pragma unroll
        for (int c = 0; c < 4; ++c) { acc1[nt][c] = 0.f; acc2[nt][c] = 0.f; }

    const float4* h4 = (const float4*)h;
    int arow0 = wid * 16 + g;

    // ---- stage A: 128 rows x K=128, bf16 hi/lo k-pairs ----
#pragma unroll
    for (int i = 0; i < 16; ++i) {
        int idx = tid + i * 256;            // 0..4095
        int row = idx >> 5, q = idx & 31;   // q: float4 index in 128-col row
        int grow = rb + row;
        float4 v = make_float4(0.f, 0.f, 0.f, 0.f);
        if (grow < N) v = h4[grow * 32 + q];
        __nv_bfloat16 bx = __float2bfloat16_rn(v.x);
        __nv_bfloat16 by = __float2bfloat16_rn(v.y);
        __nv_bfloat16 bz = __float2bfloat16_rn(v.z);
        __nv_bfloat16 bw = __float2bfloat16_rn(v.w);
        uint32_t hi0 = ((uint32_t)__bfloat16_as_ushort(by) << 16)
                     |  (uint32_t)__bfloat16_as_ushort(bx);
        uint32_t hi1 = ((uint32_t)__bfloat16_as_ushort(bw) << 16)
                     |  (uint32_t)__bfloat16_as_ushort(bz);
        uint32_t lo0 = packbf(v.x - __bfloat162float(bx),
                              v.y - __bfloat162float(by));
        uint32_t lo1 = packbf(v.z - __bfloat162float(bz),
                              v.w - __bfloat162float(bw));
        *(uint2*)(A_hi + row * SP + q * 2) = make_uint2(hi0, hi1);
        *(uint2*)(A_lo + row * SP + q * 2) = make_uint2(lo0, lo1);
    }
    // ---- stage B: copy pre-packed tiles (pad 64 -> 68 stride) ----
    {
        const uint4* wp4 = (const uint4*)wpack;   // 8192 uint4
#pragma unroll
        for (int i = 0; i < 32; ++i) {
            int idx = tid + i * 256;              // 0..8191
            int t = idx >> 11;                    // tile 0..3
            int r = idx & 2047;                   // n*16 + j
            int n = r >> 4, j = r & 15;
            uint4 v = wp4[idx];
            *(uint4*)(Bb + t * TILE_U32 + n * SP + j * 4) = v;
        }
    }
    __syncthreads();

    // ---- mma mainloop: 8 k16-steps ----
    uint32_t* B1h = Bb;
    uint32_t* B1l = Bb + TILE_U32;
    uint32_t* B2h = Bb + 2 * TILE_U32;
    uint32_t* B2l = Bb + 3 * TILE_U32;
    for (int kk = 0; kk < 8; ++kk) {
        int kp = kk * 8 + tg;
        uint32_t aH[4], aL[4];
        aH[0] = A_hi[arow0 * SP + kp];
        aH[1] = A_hi[(arow0 + 8) * SP + kp];
        aH[2] = A_hi[arow0 * SP + kp + 4];
        aH[3] = A_hi[(arow0 + 8) * SP + kp + 4];
        aL[0] = A_lo[arow0 * SP + kp];
        aL[1] = A_lo[(arow0 + 8) * SP + kp];
        aL[2] = A_lo[arow0 * SP + kp + 4];
        aL[3] = A_lo[(arow0 + 8) * SP + kp + 4];
        int rbase = g * SP + kp;                  // + nt*8*SP per tile
#pragma unroll
        for (int nt = 0; nt < 16; ++nt) {
            int o = rbase + nt * 8 * SP;
            uint32_t b1h0 = B1h[o], b1h1 = B1h[o + 4];
            uint32_t b1l0 = B1l[o], b1l1 = B1l[o + 4];
            mma16(acc1[nt], aH, b1h0, b1h1);
            mma16(acc1[nt], aL, b1h0, b1h1);
            mma16(acc1[nt], aH, b1l0, b1l1);
            uint32_t b2h0 = B2h[o], b2h1 = B2h[o + 4];
            uint32_t b2l0 = B2l[o], b2l1 = B2l[o + 4];
            mma16(acc2[nt], aH, b2h0, b2h1);
            mma16(acc2[nt], aL, b2h0, b2h1);
            mma16(acc2[nt], aH, b2l0, b2l1);
        }
    }

    // ---- attention scalars from acc1 registers ----
    {
        float p0r0 = 0.f, p1r0 = 0.f, p0r1 = 0.f, p1r1 = 0.f;
#pragma unroll
        for (int nt = 0; nt < 16; ++nt) {
            int c = nt * 8 + tg * 2;
            float w0a = s_wa[c], w0b = s_wa[c + 1];
            float w1a = s_wa[128 + c], w1b = s_wa[128 + c + 1];
            p0r0 += acc1[nt][0] * w0a + acc1[nt][1] * w0b;
            p1r0 += acc1[nt][0] * w1a + acc1[nt][1] * w1b;
            p0r1 += acc1[nt][2] * w0a + acc1[nt][3] * w0b;
            p1r1 += acc1[nt][2] * w1a + acc1[nt][3] * w1b;
        }
#pragma unroll
        for (int o = 1; o <= 2; o <<= 1) {
            p0r0 += __shfl_xor_sync(0xffffffffu, p0r0, o);
            p1r0 += __shfl_xor_sync(0xffffffffu, p1r0, o);
            p0r1 += __shfl_xor_sync(0xffffffffu, p0r1, o);
            p1r1 += __shfl_xor_sync(0xffffffffu, p1r1, o);
        }
        if (tg == 0) {
            int rw = rb + wid * 16 + g;
            if (rw < N)     { asout[rw]     = p0r0; adout[rw]     = p1r0; }
            if (rw + 8 < N) { asout[rw + 8] = p0r1; adout[rw + 8] = p1r1; }
        }
    }

    // ---- coalesced epilogue via smem roundtrip (buf overlays B region) ----
    float* buf = (float*)Bb;                       // [128][132] floats
#pragma unroll
    for (int m = 0; m < 2; ++m) {
        float (*acc)[4] = m ? acc2 : acc1;
        float* gout = m ? ziout : zout;
        __syncthreads();
        int rw0 = wid * 16 + g;
#pragma unroll
        for (int nt = 0; nt < 16; ++nt) {
            int c = nt * 8 + tg * 2;
            *(float2*)(buf + rw0 * 132 + c)       = make_float2(acc[nt][0], acc[nt][1]);
            *(float2*)(buf + (rw0 + 8) * 132 + c) = make_float2(acc[nt][2], acc[nt][3]);
        }
        __syncthreads();
#pragma unroll
        for (int i = 0; i < 16; ++i) {
            int idx = tid + i * 256;
            int row = idx >> 5, q = idx & 31;
            int grow = rb + row;
            if (grow < N)
                ((float4*)gout)[grow * 32 + q] = *(float4*)(buf + row * 132 + q * 4);
        }
    }
}

// ------------------------------------------------------------------
// Segment softmax + weighted aggregation + residual relu (warp per node),
// over node range [n0, n1), reading the given z/zi/asrc/adst bank.
// ------------------------------------------------------------------
__global__ void k_aggregate(const float* __restrict__ W0l,
                            const float* __restrict__ Wal,
                            float* __restrict__ out, int n0, int n1,
                            const float* __restrict__ zin,
                            const float* __restrict__ ziin,
                            const float* __restrict__ asin_,
                            const float* __restrict__ adin) {
    int n = n0 + ((blockIdx.x * blockDim.x + threadIdx.x) >> 5);
    int lane = threadIdx.x & 31;
    if (n >= n1) return;

    int beg = g_rowptr[n], end = g_rowptr[n + 1];
    float coef = W0l[0] * Wal[2 * Dq];
    float ad = adin[n];

    float ssum = 0.f;
    float4 accA = make_float4(0.f, 0.f, 0.f, 0.f);
    float4 accB = make_float4(0.f, 0.f, 0.f, 0.f);
    const float4* z4 = (const float4*)zin;

    for (int b = beg; b < end; b += 32) {
        int cnt = min(32, end - b);
        int s = 0;
        float ex = 0.f;
        if (lane < cnt) {
            uint2 ed = g_edge[b + lane];
            s = (int)ed.x;
            float x = asin_[s] + ad + __uint_as_float(ed.y) * coef;
            float e = x > 0.f ? x : 0.01f * x;
            ex = __expf(e);
        }
        float ps = ex;
#pragma unroll
        for (int o = 16; o; o >>= 1) ps += __shfl_xor_sync(0xffffffffu, ps, o);
        ssum += ps;
        int j = 0;
        for (; j + 2 <= cnt; j += 2) {
            int   s0 = __shfl_sync(0xffffffffu, s, j);
            float e0 = __shfl_sync(0xffffffffu, ex, j);
            int   s1 = __shfl_sync(0xffffffffu, s, j + 1);
            float e1 = __shfl_sync(0xffffffffu, ex, j + 1);
            float4 z0 = z4[s0 * 32 + lane];
            float4 z1 = z4[s1 * 32 + lane];
            accA.x += e0 * z0.x; accA.y += e0 * z0.y;
            accA.z += e0 * z0.z; accA.w += e0 * z0.w;
            accB.x += e1 * z1.x; accB.y += e1 * z1.y;
            accB.z += e1 * z1.z; accB.w += e1 * z1.w;
        }
        if (j < cnt) {
            int   s0 = __shfl_sync(0xffffffffu, s, j);
            float e0 = __shfl_sync(0xffffffffu, ex, j);
            float4 z0 = z4[s0 * 32 + lane];
            accA.x += e0 * z0.x; accA.y += e0 * z0.y;
            accA.z += e0 * z0.z; accA.w += e0 * z0.w;
        }
    }
    float inv = (end > beg) ? 1.f / ssum : 0.f;

    const float4* zi4 = (const float4*)ziin;
    float4 zi = zi4[n * 32 + lane];
    float4 o;
    o.x = fmaxf(zi.x + (accA.x + accB.x) * inv, 0.f);
    o.y = fmaxf(zi.y + (accA.y + accB.y) * inv, 0.f);
    o.z = fmaxf(zi.z + (accA.z + accB.z) * inv, 0.f);
    o.w = fmaxf(zi.w + (accA.w + accB.w) * inv, 0.f);
    ((float4*)out)[n * 32 + lane] = o;
}

// ------------------------------------------------------------------
extern "C" void kernel_launch(void* const* d_in, const int* in_sizes, int n_in,
                              void* d_out, int out_size) {
    const float* attr = (const float*)d_in[0];
    const float* dval = (const float*)d_in[1];
    const int*   src  = (const int*)d_in[2];
    const int*   dst  = (const int*)d_in[3];
    const float* W0   = (const float*)d_in[4];
    const float* W1   = (const float*)d_in[5];
    const float* W2   = (const float*)d_in[6];
    const float* Wa   = (const float*)d_in[7];

    int N = in_sizes[0] / Dq;
    int E = in_sizes[2];
    int L = in_sizes[4];

    // ---- lazy-once host resources (no per-call create -> no leak delta) ----
    static cudaStream_t s1 = nullptr, s2 = nullptr;
    static cudaEvent_t evFork, evCsr, evEnd;
    static cudaEvent_t evAa[8], evGb[8];
    static bool inited = false;
    if (!inited) {
        cudaStreamCreateWithFlags(&s1, cudaStreamNonBlocking);
        cudaStreamCreateWithFlags(&s2, cudaStreamNonBlocking);
        cudaEventCreateWithFlags(&evFork, cudaEventDisableTiming);
        cudaEventCreateWithFlags(&evCsr, cudaEventDisableTiming);
        cudaEventCreateWithFlags(&evEnd, cudaEventDisableTiming);
        for (int i = 0; i < 8; ++i) {
            cudaEventCreateWithFlags(&evAa[i], cudaEventDisableTiming);
            cudaEventCreateWithFlags(&evGb[i], cudaEventDisableTiming);
        }
        cudaFuncSetAttribute(k_gemm_mma,
                             cudaFuncAttributeMaxDynamicSharedMemorySize,
                             DYN_SMEM);
        inited = true;
    }

    void *pA = nullptr, *pB = nullptr, *pW = nullptr;
    void *pZ = nullptr, *pZi = nullptr, *pAs = nullptr, *pAd = nullptr;
    cudaGetSymbolAddress(&pA, g_hA);
    cudaGetSymbolAddress(&pB, g_hB);
    cudaGetSymbolAddress(&pW, g_Wpack);
    cudaGetSymbolAddress(&pZ, g_zb);
    cudaGetSymbolAddress(&pZi, g_zib);
    cudaGetSymbolAddress(&pAs, g_asb);
    cudaGetSymbolAddress(&pAd, g_adb);
    float* zB[2]  = { (float*)pZ,  (float*)pZ  + (size_t)MAXN * Dq };
    float* ziB[2] = { (float*)pZi, (float*)pZi + (size_t)MAXN * Dq };
    float* asB[2] = { (float*)pAs, (float*)pAs + MAXN };
    float* adB[2] = { (float*)pAd, (float*)pAd + MAXN };

    int scanBlocks = (N + SCAN_BLK - 1) / SCAN_BLK;
    int gemmBlocks = (N + 127) / 128;
    int gBlocksA = (gemmBlocks + 1) / 2;
    int gBlocksB = gemmBlocks - gBlocksA;
    int rowSplit = gBlocksA * 128;
    if (rowSplit > N) rowSplit = N;
    int aggBlocksA = (rowSplit * 32 + 255) / 256;
    int aggBlocksB = ((N - rowSplit) * 32 + 255) / 256;
    int aggBlocksFull = (N * 32 + 255) / 256;

    // ---- fork: CSR build on s2 (overlaps packW + layer-0 GEMM on s0) ----
    cudaEventRecord(evFork, 0);
    cudaStreamWaitEvent(s2, evFork, 0);
    k_zero_deg<<<(N + 255) / 256, 256, 0, s2>>>(N);
    k_hist<<<(E + 255) / 256, 256, 0, s2>>>(dst, E);
    k_scan1<<<scanBlocks, SCAN_BLK, 0, s2>>>(N);
    k_scan2<<<1, 64, 0, s2>>>(scanBlocks);
    k_scan3<<<scanBlocks, SCAN_BLK, 0, s2>>>(N, scanBlocks);
    k_scatter<<<(E + 255) / 256, 256, 0, s2>>>(src, dst, dval, E);
    cudaEventRecord(evCsr, s2);

    // ---- s0: W pack + full layer-0 GEMM into bank 0 ----
    k_packW<<<(L * 16384 + 255) / 256, 256>>>(W1, W2, L);
    k_gemm_mma<<<gemmBlocks, 256, DYN_SMEM>>>(attr, (const uint32_t*)pW,
                                              Wa, N, 0,
                                              zB[0], ziB[0], asB[0], adB[0]);
    cudaStreamWaitEvent(0, evCsr, 0);

    // ---- staggered layer pipeline (banked intermediates, hazard-free) ----
    for (int l = 0; l < L; ++l) {
        int p = l & 1, q = (l + 1) & 1;
        const float* Wal = Wa + (size_t)l * (2 * Dq + 1);
        float* hout = (l == L - 1) ? (float*)d_out
                                   : ((l & 1) ? (float*)pB : (float*)pA);
        if (l < L - 1) {
            const uint32_t* wp = (const uint32_t*)pW + (size_t)(l + 1) * 4 * 8192;
            const float* Wan = Wa + (size_t)(l + 1) * (2 * Dq + 1);

            // s0: A_l^a (reads bank p), then G_{l+1}^a (writes bank q)
            k_aggregate<<<aggBlocksA, 256, 0, 0>>>(W0 + l, Wal, hout,
                                                   0, rowSplit,
                                                   zB[p], ziB[p], asB[p], adB[p]);
            cudaEventRecord(evAa[l], 0);
            cudaStreamWaitEvent(s1, evAa[l], 0);
            k_gemm_mma<<<gBlocksA, 256, DYN_SMEM, 0>>>(hout, wp, Wan, N, 0,
                                                       zB[q], ziB[q],
                                                       asB[q], adB[q]);
            // s1: A_l^b (reads bank p) then G_{l+1}^b (writes bank q)
            if (aggBlocksB > 0)
                k_aggregate<<<aggBlocksB, 256, 0, s1>>>(W0 + l, Wal, hout,
                                                        rowSplit, N,
                                                        zB[p], ziB[p],
                                                        asB[p], adB[p]);
            if (gBlocksB > 0)
                k_gemm_mma<<<gBlocksB, 256, DYN_SMEM, s1>>>(hout, wp, Wan,
                                                            N, rowSplit,
                                                            zB[q], ziB[q],
                                                            asB[q], adB[q]);
            cudaEventRecord(evGb[l], s1);
            cudaStreamWaitEvent(0, evGb[l], 0);
        } else {
            // last layer: single full aggregate on s0 (writes d_out)
            k_aggregate<<<aggBlocksFull, 256, 0, 0>>>(W0 + l, Wal, hout, 0, N,
                                                      zB[p], ziB[p],
                                                      asB[p], adB[p]);
        }
    }
    // join s1 back into the capture stream
    cudaEventRecord(evEnd, s1);
    cudaStreamWaitEvent(0, evEnd, 0);
}

// round 15
// speedup vs baseline: 1.1005x; 1.1005x over previous
#include <cuda_runtime.h>
#include <cuda_bf16.h>
#include <cuda_fp16.h>
#include <cstdint>

#define Dq 128          // feature dim (fixed by problem)
#define MAXN 40960
#define MAXE 665600
#define SCAN_BLK 1024
#define MAX_SCAN_BLOCKS ((MAXN + SCAN_BLK - 1) / SCAN_BLK)

// ---- static device scratch (allocation-free rule) ----
__device__ uint4 g_zh[MAXN * 16];   // z as packed half2: 64 half2 per row
__device__ float g_zi[MAXN * Dq];   // h @ W2 (fp32, residual path)
__device__ float g_hA[MAXN * Dq];   // layer ping
__device__ float g_hB[MAXN * Dq];   // layer pong
__device__ float g_asrc[MAXN];
__device__ float g_adst[MAXN];
__device__ int   g_deg[MAXN];
__device__ int   g_excl[MAXN];
__device__ int   g_btot[MAX_SCAN_BLOCKS];
__device__ int   g_boff[MAX_SCAN_BLOCKS + 1];
__device__ int   g_rowptr[MAXN + 1];
__device__ int   g_cursor[MAXN];
__device__ uint2 g_edge[MAXE];      // CSR (by dst): {src, d-bits} packed
__device__ uint32_t g_Wpack[3 * 4 * 8192];  // per layer: B1h,B1l,B2h,B2l [n=128][kp=64]

// pack two floats as bf16x2 (lo k in low 16 bits)
__device__ __forceinline__ uint32_t packbf(float a, float b) {
    unsigned short ua = __bfloat16_as_ushort(__float2bfloat16_rn(a));
    unsigned short ub = __bfloat16_as_ushort(__float2bfloat16_rn(b));
    return ((uint32_t)ub << 16) | (uint32_t)ua;
}

// m16n8k16 bf16 MMA, fp32 accumulate in place
__device__ __forceinline__ void mma16(float* c, const uint32_t* a,
                                      uint32_t b0, uint32_t b1) {
    asm volatile("mma.sync.aligned.m16n8k16.row.col.f32.bf16.bf16.f32 "
                 "{%0,%1,%2,%3}, {%4,%5,%6,%7}, {%8,%9}, {%0,%1,%2,%3};"
                 : "+f"(c[0]), "+f"(c[1]), "+f"(c[2]), "+f"(c[3])
                 : "r"(a[0]), "r"(a[1]), "r"(a[2]), "r"(a[3]),
                   "r"(b0), "r"(b1));
}

// ------------------------------------------------------------------
// W packing: all L layers, W1/W2 -> n-major bf16 hi/lo k-pair tiles
// ------------------------------------------------------------------
__global__ void k_packW(const float* __restrict__ W1,
                        const float* __restrict__ W2, int L) {
    int idx = blockIdx.x * blockDim.x + threadIdx.x;
    int total = L * 2 * 8192;
    if (idx >= total) return;
    int l = idx / 16384;
    int r = idx - l * 16384;
    int m = r >> 13;               // 0 = W1, 1 = W2
    int rr = r & 8191;
    int kp = rr >> 7;              // 0..63
    int n = rr & 127;
    const float* W = (m ? W2 : W1) + (size_t)l * Dq * Dq;
    float x0 = W[(2 * kp) * 128 + n];
    float x1 = W[(2 * kp + 1) * 128 + n];
    __nv_bfloat16 b0 = __float2bfloat16_rn(x0);
    __nv_bfloat16 b1 = __float2bfloat16_rn(x1);
    uint32_t hi = ((uint32_t)__bfloat16_as_ushort(b1) << 16)
                |  (uint32_t)__bfloat16_as_ushort(b0);
    uint32_t lo = packbf(x0 - __bfloat162float(b0), x1 - __bfloat162float(b1));
    uint32_t* base = g_Wpack + (size_t)l * 4 * 8192;
    base[(2 * m + 0) * 8192 + n * 64 + kp] = hi;
    base[(2 * m + 1) * 8192 + n * 64 + kp] = lo;
}

// ------------------------------------------------------------------
// CSR build
// ------------------------------------------------------------------
__global__ void k_zero_deg(int N) {
    int i = blockIdx.x * blockDim.x + threadIdx.x;
    if (i < N) g_deg[i] = 0;
}

__global__ void k_hist(const int* __restrict__ dst, int E) {
    int e = blockIdx.x * blockDim.x + threadIdx.x;
    if (e < E) atomicAdd(&g_deg[dst[e]], 1);
}

// phase 1: per-block exclusive scan of a 1024 chunk + block total
__global__ void k_scan1(int N) {
    __shared__ int wtot[32];
    int tid = threadIdx.x, lane = tid & 31, wid = tid >> 5;
    int i = blockIdx.x * SCAN_BLK + tid;
    int v = (i < N) ? g_deg[i] : 0;
    int x = v;
#pragma unroll
    for (int o = 1; o < 32; o <<= 1) {
        int t = __shfl_up_sync(0xffffffffu, x, o);
        if (lane >= o) x += t;
    }
    if (lane == 31) wtot[wid] = x;
    __syncthreads();
    if (wid == 0) {
        int w = wtot[lane];
#pragma unroll
        for (int o = 1; o < 32; o <<= 1) {
            int t = __shfl_up_sync(0xffffffffu, w, o);
            if (lane >= o) w += t;
        }
        wtot[lane] = w;
    }
    __syncthreads();
    int pre = (wid > 0 ? wtot[wid - 1] : 0);
    if (i < N) g_excl[i] = pre + x - v;
    if (tid == SCAN_BLK - 1) g_btot[blockIdx.x] = pre + x;
}

// phase 2: scan the block totals (tiny)
__global__ void k_scan2(int nblocks) {
    int lane = threadIdx.x & 31, wid = threadIdx.x >> 5;
    __shared__ int wtot[32];
    int i = threadIdx.x;
    int v = (i < nblocks) ? g_btot[i] : 0;
    int x = v;
#pragma unroll
    for (int o = 1; o < 32; o <<= 1) {
        int t = __shfl_up_sync(0xffffffffu, x, o);
        if (lane >= o) x += t;
    }
    if (lane == 31) wtot[wid] = x;
    __syncthreads();
    if (wid == 0) {
        int w = (lane < 2) ? wtot[lane] : 0;
#pragma unroll
        for (int o = 1; o < 32; o <<= 1) {
            int t = __shfl_up_sync(0xffffffffu, w, o);
            if (lane >= o) w += t;
        }
        wtot[lane] = w;
    }
    __syncthreads();
    int pre = (wid > 0 ? wtot[wid - 1] : 0);
    if (i <= nblocks) g_boff[i] = pre + x - v;
    if (i == nblocks) g_boff[i] = pre + x - v;
}

// phase 3: add block offsets, emit rowptr + cursor
__global__ void k_scan3(int N, int nblocks) {
    int i = blockIdx.x * SCAN_BLK + threadIdx.x;
    if (i < N) {
        int r = g_excl[i] + g_boff[blockIdx.x];
        g_rowptr[i] = r;
        g_cursor[i] = r;
    }
    if (i == 0) g_rowptr[N] = g_boff[nblocks];
}

__global__ void k_scatter(const int* __restrict__ src, const int* __restrict__ dst,
                          const float* __restrict__ dval, int E) {
    int e = blockIdx.x * blockDim.x + threadIdx.x;
    if (e < E) {
        int p = atomicAdd(&g_cursor[dst[e]], 1);
        g_edge[p] = make_uint2((uint32_t)src[e], __float_as_uint(dval[e]));
    }
}

// ------------------------------------------------------------------
// Tensor-core GEMM via mma.sync m16n8k16 bf16 (3-term hi/lo split):
//   z(fp16 packed) = h@W1, zi(fp32) = h@W2. 128x128 tile, K=128 in smem.
// ------------------------------------------------------------------
#define SP 68                           // row stride in u32 (64 k-pairs + 4 pad)
#define TILE_U32 8704                   // 128 * 68
#define DYN_SMEM (52224 * 4)            // 208896 bytes

__global__ __launch_bounds__(256, 1)
void k_gemm_mma(const float* __restrict__ h,
                const uint32_t* __restrict__ wpack,
                const float* __restrict__ Wal,
                int N) {
    extern __shared__ uint32_t dsu[];
    __shared__ float s_wa[256];

    uint32_t* A_hi = dsu;
    uint32_t* A_lo = dsu + TILE_U32;
    uint32_t* Bb   = dsu + 2 * TILE_U32;   // 4 tiles: B1h,B1l,B2h,B2l

    int tid = threadIdx.x, wid = tid >> 5, lane = tid & 31;
    int g = lane >> 2, tg = lane & 3;
    int rb = blockIdx.x * 128;

    s_wa[tid] = Wal[tid];

    float acc1[16][4], acc2[16][4];
#pragma unroll
    for (int nt = 0; nt < 16; ++nt)
#pragma unroll
        for (int c = 0; c < 4; ++c) { acc1[nt][c] = 0.f; acc2[nt][c] = 0.f; }

    const float4* h4 = (const float4*)h;
    int arow0 = wid * 16 + g;

    // ---- stage A: 128 rows x K=128, bf16 hi/lo k-pairs ----
#pragma unroll
    for (int i = 0; i < 16; ++i) {
        int idx = tid + i * 256;            // 0..4095
        int row = idx >> 5, q = idx & 31;
        int grow = rb + row;
        float4 v = make_float4(0.f, 0.f, 0.f, 0.f);
        if (grow < N) v = h4[grow * 32 + q];
        __nv_bfloat16 bx = __float2bfloat16_rn(v.x);
        __nv_bfloat16 by = __float2bfloat16_rn(v.y);
        __nv_bfloat16 bz = __float2bfloat16_rn(v.z);
        __nv_bfloat16 bw = __float2bfloat16_rn(v.w);
        uint32_t hi0 = ((uint32_t)__bfloat16_as_ushort(by) << 16)
                     |  (uint32_t)__bfloat16_as_ushort(bx);
        uint32_t hi1 = ((uint32_t)__bfloat16_as_ushort(bw) << 16)
                     |  (uint32_t)__bfloat16_as_ushort(bz);
        uint32_t lo0 = packbf(v.x - __bfloat162float(bx),
                              v.y - __bfloat162float(by));
        uint32_t lo1 = packbf(v.z - __bfloat162float(bz),
                              v.w - __bfloat162float(bw));
        *(uint2*)(A_hi + row * SP + q * 2) = make_uint2(hi0, hi1);
        *(uint2*)(A_lo + row * SP + q * 2) = make_uint2(lo0, lo1);
    }
    // ---- stage B: copy pre-packed tiles (pad 64 -> 68 stride) ----
    {
        const uint4* wp4 = (const uint4*)wpack;   // 8192 uint4
#pragma unroll
        for (int i = 0; i < 32; ++i) {
            int idx = tid + i * 256;
            int t = idx >> 11;
            int r = idx & 2047;
            int n = r >> 4, j = r & 15;
            uint4 v = wp4[idx];
            *(uint4*)(Bb + t * TILE_U32 + n * SP + j * 4) = v;
        }
    }
    __syncthreads();

    // ---- mma mainloop: 8 k16-steps ----
    uint32_t* B1h = Bb;
    uint32_t* B1l = Bb + TILE_U32;
    uint32_t* B2h = Bb + 2 * TILE_U32;
    uint32_t* B2l = Bb + 3 * TILE_U32;
    for (int kk = 0; kk < 8; ++kk) {
        int kp = kk * 8 + tg;
        uint32_t aH[4], aL[4];
        aH[0] = A_hi[arow0 * SP + kp];
        aH[1] = A_hi[(arow0 + 8) * SP + kp];
        aH[2] = A_hi[arow0 * SP + kp + 4];
        aH[3] = A_hi[(arow0 + 8) * SP + kp + 4];
        aL[0] = A_lo[arow0 * SP + kp];
        aL[1] = A_lo[(arow0 + 8) * SP + kp];
        aL[2] = A_lo[arow0 * SP + kp + 4];
        aL[3] = A_lo[(arow0 + 8) * SP + kp + 4];
        int rbase = g * SP + kp;
#pragma unroll
        for (int nt = 0; nt < 16; ++nt) {
            int o = rbase + nt * 8 * SP;
            uint32_t b1h0 = B1h[o], b1h1 = B1h[o + 4];
            uint32_t b1l0 = B1l[o], b1l1 = B1l[o + 4];
            mma16(acc1[nt], aH, b1h0, b1h1);
            mma16(acc1[nt], aL, b1h0, b1h1);
            mma16(acc1[nt], aH, b1l0, b1l1);
            uint32_t b2h0 = B2h[o], b2h1 = B2h[o + 4];
            uint32_t b2l0 = B2l[o], b2l1 = B2l[o + 4];
            mma16(acc2[nt], aH, b2h0, b2h1);
            mma16(acc2[nt], aL, b2h0, b2h1);
            mma16(acc2[nt], aH, b2l0, b2l1);
        }
    }

    // ---- attention scalars from acc1 registers ----
    {
        float p0r0 = 0.f, p1r0 = 0.f, p0r1 = 0.f, p1r1 = 0.f;
#pragma unroll
        for (int nt = 0; nt < 16; ++nt) {
            int c = nt * 8 + tg * 2;
            float w0a = s_wa[c], w0b = s_wa[c + 1];
            float w1a = s_wa[128 + c], w1b = s_wa[128 + c + 1];
            p0r0 += acc1[nt][0] * w0a + acc1[nt][1] * w0b;
            p1r0 += acc1[nt][0] * w1a + acc1[nt][1] * w1b;
            p0r1 += acc1[nt][2] * w0a + acc1[nt][3] * w0b;
            p1r1 += acc1[nt][2] * w1a + acc1[nt][3] * w1b;
        }
#pragma unroll
        for (int o = 1; o <= 2; o <<= 1) {
            p0r0 += __shfl_xor_sync(0xffffffffu, p0r0, o);
            p1r0 += __shfl_xor_sync(0xffffffffu, p1r0, o);
            p0r1 += __shfl_xor_sync(0xffffffffu, p0r1, o);
            p1r1 += __shfl_xor_sync(0xffffffffu, p1r1, o);
        }
        if (tg == 0) {
            int rw = rb + wid * 16 + g;
            if (rw < N)     { g_asrc[rw]     = p0r0; g_adst[rw]     = p1r0; }
            if (rw + 8 < N) { g_asrc[rw + 8] = p0r1; g_adst[rw + 8] = p1r1; }
        }
    }

    // ---- epilogue via smem roundtrip ----
    float* buf = (float*)Bb;                       // [128][132] floats
    // z: convert to packed half2 rows (256 B/row)
    {
        __syncthreads();
        int rw0 = wid * 16 + g;
#pragma unroll
        for (int nt = 0; nt < 16; ++nt) {
            int c = nt * 8 + tg * 2;
            *(float2*)(buf + rw0 * 132 + c)       = make_float2(acc1[nt][0], acc1[nt][1]);
            *(float2*)(buf + (rw0 + 8) * 132 + c) = make_float2(acc1[nt][2], acc1[nt][3]);
        }
        __syncthreads();
#pragma unroll
        for (int i = 0; i < 8; ++i) {
            int idx = tid + i * 256;              // 0..2047
            int row = idx >> 4, q = idx & 15;     // q: uint4 index in row
            int grow = rb + row;
            if (grow < N) {
                const float* p = buf + row * 132 + q * 8;
                __half2 a = __floats2half2_rn(p[0], p[1]);
                __half2 b = __floats2half2_rn(p[2], p[3]);
                __half2 c2 = __floats2half2_rn(p[4], p[5]);
                __half2 d = __floats2half2_rn(p[6], p[7]);
                uint4 v;
                v.x = *(uint32_t*)&a; v.y = *(uint32_t*)&b;
                v.z = *(uint32_t*)&c2; v.w = *(uint32_t*)&d;
                g_zh[(size_t)grow * 16 + q] = v;
            }
        }
    }
    // zi: fp32 stores
    {
        __syncthreads();
        int rw0 = wid * 16 + g;
#pragma unroll
        for (int nt = 0; nt < 16; ++nt) {
            int c = nt * 8 + tg * 2;
            *(float2*)(buf + rw0 * 132 + c)       = make_float2(acc2[nt][0], acc2[nt][1]);
            *(float2*)(buf + (rw0 + 8) * 132 + c) = make_float2(acc2[nt][2], acc2[nt][3]);
        }
        __syncthreads();
#pragma unroll
        for (int i = 0; i < 16; ++i) {
            int idx = tid + i * 256;
            int row = idx >> 5, q = idx & 31;
            int grow = rb + row;
            if (grow < N)
                ((float4*)g_zi)[grow * 32 + q] = *(float4*)(buf + row * 132 + q * 4);
        }
    }
}

// ------------------------------------------------------------------
// Segment softmax + weighted aggregation + residual relu (warp per node).
// z gathered as packed half2 rows (256 B), accumulated in fp32.
// ------------------------------------------------------------------
__global__ void k_aggregate(const float* __restrict__ W0l,
                            const float* __restrict__ Wal,
                            float* __restrict__ out, int N) {
    int n = (blockIdx.x * blockDim.x + threadIdx.x) >> 5;
    int lane = threadIdx.x & 31;
    if (n >= N) return;

    int beg = g_rowptr[n], end = g_rowptr[n + 1];
    float coef = W0l[0] * Wal[2 * Dq];
    float ad = g_adst[n];

    float ssum = 0.f;
    float4 accA = make_float4(0.f, 0.f, 0.f, 0.f);
    float4 accB = make_float4(0.f, 0.f, 0.f, 0.f);
    const uint2* zh = (const uint2*)g_zh;     // 32 uint2 (8B) per row

    for (int b = beg; b < end; b += 32) {
        int cnt = min(32, end - b);
        int s = 0;
        float ex = 0.f;
        if (lane < cnt) {
            uint2 ed = g_edge[b + lane];
            s = (int)ed.x;
            float x = g_asrc[s] + ad + __uint_as_float(ed.y) * coef;
            float e = x > 0.f ? x : 0.01f * x;
            ex = __expf(e);
        }
        float ps = ex;
#pragma unroll
        for (int o = 16; o; o >>= 1) ps += __shfl_xor_sync(0xffffffffu, ps, o);
        ssum += ps;
        int j = 0;
        for (; j + 2 <= cnt; j += 2) {
            int   s0 = __shfl_sync(0xffffffffu, s, j);
            float e0 = __shfl_sync(0xffffffffu, ex, j);
            int   s1 = __shfl_sync(0xffffffffu, s, j + 1);
            float e1 = __shfl_sync(0xffffffffu, ex, j + 1);
            uint2 r0 = zh[(size_t)s0 * 32 + lane];
            uint2 r1 = zh[(size_t)s1 * 32 + lane];
            float2 f0a = __half22float2(*reinterpret_cast<__half2*>(&r0.x));
            float2 f0b = __half22float2(*reinterpret_cast<__half2*>(&r0.y));
            float2 f1a = __half22float2(*reinterpret_cast<__half2*>(&r1.x));
            float2 f1b = __half22float2(*reinterpret_cast<__half2*>(&r1.y));
            accA.x += e0 * f0a.x; accA.y += e0 * f0a.y;
            accA.z += e0 * f0b.x; accA.w += e0 * f0b.y;
            accB.x += e1 * f1a.x; accB.y += e1 * f1a.y;
            accB.z += e1 * f1b.x; accB.w += e1 * f1b.y;
        }
        if (j < cnt) {
            int   s0 = __shfl_sync(0xffffffffu, s, j);
            float e0 = __shfl_sync(0xffffffffu, ex, j);
            uint2 r0 = zh[(size_t)s0 * 32 + lane];
            float2 f0a = __half22float2(*reinterpret_cast<__half2*>(&r0.x));
            float2 f0b = __half22float2(*reinterpret_cast<__half2*>(&r0.y));
            accA.x += e0 * f0a.x; accA.y += e0 * f0a.y;
            accA.z += e0 * f0b.x; accA.w += e0 * f0b.y;
        }
    }
    float inv = (end > beg) ? 1.f / ssum : 0.f;

    // lane owns features [lane*4, lane*4+4) -> matches zi float4 layout
    const float4* zi4 = (const float4*)g_zi;
    float4 zi = zi4[n * 32 + lane];
    float4 o;
    o.x = fmaxf(zi.x + (accA.x + accB.x) * inv, 0.f);
    o.y = fmaxf(zi.y + (accA.y + accB.y) * inv, 0.f);
    o.z = fmaxf(zi.z + (accA.z + accB.z) * inv, 0.f);
    o.w = fmaxf(zi.w + (accA.w + accB.w) * inv, 0.f);
    ((float4*)out)[n * 32 + lane] = o;
}

// ------------------------------------------------------------------
extern "C" void kernel_launch(void* const* d_in, const int* in_sizes, int n_in,
                              void* d_out, int out_size) {
    const float* attr = (const float*)d_in[0];
    const float* dval = (const float*)d_in[1];
    const int*   src  = (const int*)d_in[2];
    const int*   dst  = (const int*)d_in[3];
    const float* W0   = (const float*)d_in[4];
    const float* W1   = (const float*)d_in[5];
    const float* W2   = (const float*)d_in[6];
    const float* Wa   = (const float*)d_in[7];

    int N = in_sizes[0] / Dq;
    int E = in_sizes[2];
    int L = in_sizes[4];

    // ---- lazy-once host resources (no per-call create -> no leak delta) ----
    static cudaStream_t s2 = nullptr;
    static cudaEvent_t evFork, evCsr;
    static bool inited = false;
    if (!inited) {
        cudaStreamCreateWithFlags(&s2, cudaStreamNonBlocking);
        cudaEventCreateWithFlags(&evFork, cudaEventDisableTiming);
        cudaEventCreateWithFlags(&evCsr, cudaEventDisableTiming);
        cudaFuncSetAttribute(k_gemm_mma,
                             cudaFuncAttributeMaxDynamicSharedMemorySize,
                             DYN_SMEM);
        inited = true;
    }

    void *pA = nullptr, *pB = nullptr, *pW = nullptr;
    cudaGetSymbolAddress(&pA, g_hA);
    cudaGetSymbolAddress(&pB, g_hB);
    cudaGetSymbolAddress(&pW, g_Wpack);

    int scanBlocks = (N + SCAN_BLK - 1) / SCAN_BLK;
    int gemmBlocks = (N + 127) / 128;
    int nodeWarpBlocks = (N * 32 + 255) / 256;

    // ---- fork: CSR build on s2 (overlaps packW + layer-0 GEMM on s0) ----
    cudaEventRecord(evFork, 0);
    cudaStreamWaitEvent(s2, evFork, 0);
    k_zero_deg<<<(N + 255) / 256, 256, 0, s2>>>(N);
    k_hist<<<(E + 255) / 256, 256, 0, s2>>>(dst, E);
    k_scan1<<<scanBlocks, SCAN_BLK, 0, s2>>>(N);
    k_scan2<<<1, 64, 0, s2>>>(scanBlocks);
    k_scan3<<<scanBlocks, SCAN_BLK, 0, s2>>>(N, scanBlocks);
    k_scatter<<<(E + 255) / 256, 256, 0, s2>>>(src, dst, dval, E);
    cudaEventRecord(evCsr, s2);

    // ---- s0: W pack + layer-0 GEMM overlap the CSR build ----
    k_packW<<<(L * 16384 + 255) / 256, 256>>>(W1, W2, L);

    const float* hin = attr;
    for (int l = 0; l < L; ++l) {
        float* hout = (l == L - 1) ? (float*)d_out
                                   : ((l & 1) ? (float*)pB : (float*)pA);
        k_gemm_mma<<<gemmBlocks, 256, DYN_SMEM>>>(
            hin, (const uint32_t*)pW + (size_t)l * 4 * 8192,
            Wa + (size_t)l * (2 * Dq + 1), N);
        if (l == 0) cudaStreamWaitEvent(0, evCsr, 0);
        k_aggregate<<<nodeWarpBlocks, 256>>>(W0 + l,
                                             Wa + (size_t)l * (2 * Dq + 1),
                                             hout, N);
        hin = hout;
    }
}

// round 16
// speedup vs baseline: 1.1564x; 1.0508x over previous
#include <cuda_runtime.h>
#include <cuda_bf16.h>
#include <cuda_fp16.h>
#include <cstdint>

#define Dq 128          // feature dim (fixed by problem)
#define MAXN 40960
#define MAXE 665600
#define SCAN_BLK 1024
#define MAX_SCAN_BLOCKS ((MAXN + SCAN_BLK - 1) / SCAN_BLK)

// ---- static device scratch (allocation-free rule) ----
__device__ uint4  g_zh[MAXN * 16];   // z as packed half2: 64 half2 per row
__device__ float  g_zi[MAXN * Dq];   // h @ W2 (fp32, residual path)
__device__ float  g_hA[MAXN * Dq];   // layer ping
__device__ float  g_hB[MAXN * Dq];   // layer pong
__device__ float2 g_as2[MAXN];       // attn scalar partials {nh0, nh1}
__device__ float2 g_ad2[MAXN];
__device__ int    g_deg[MAXN];
__device__ int    g_excl[MAXN];
__device__ int    g_btot[MAX_SCAN_BLOCKS];
__device__ int    g_boff[MAX_SCAN_BLOCKS + 1];
__device__ int    g_rowptr[MAXN + 1];
__device__ int    g_cursor[MAXN];
__device__ uint2  g_edge[MAXE];      // CSR (by dst): {src, d-bits} packed
__device__ uint32_t g_Wpack[3 * 4 * 8192];  // per layer: B1h,B1l,B2h,B2l [n=128][kp=64]

// pack two floats as bf16x2 (lo k in low 16 bits)
__device__ __forceinline__ uint32_t packbf(float a, float b) {
    unsigned short ua = __bfloat16_as_ushort(__float2bfloat16_rn(a));
    unsigned short ub = __bfloat16_as_ushort(__float2bfloat16_rn(b));
    return ((uint32_t)ub << 16) | (uint32_t)ua;
}

// m16n8k16 bf16 MMA, fp32 accumulate in place
__device__ __forceinline__ void mma16(float* c, const uint32_t* a,
                                      uint32_t b0, uint32_t b1) {
    asm volatile("mma.sync.aligned.m16n8k16.row.col.f32.bf16.bf16.f32 "
                 "{%0,%1,%2,%3}, {%4,%5,%6,%7}, {%8,%9}, {%0,%1,%2,%3};"
                 : "+f"(c[0]), "+f"(c[1]), "+f"(c[2]), "+f"(c[3])
                 : "r"(a[0]), "r"(a[1]), "r"(a[2]), "r"(a[3]),
                   "r"(b0), "r"(b1));
}

// ------------------------------------------------------------------
// W packing: all L layers, W1/W2 -> n-major bf16 hi/lo k-pair tiles
// ------------------------------------------------------------------
__global__ void k_packW(const float* __restrict__ W1,
                        const float* __restrict__ W2, int L) {
    int idx = blockIdx.x * blockDim.x + threadIdx.x;
    int total = L * 2 * 8192;
    if (idx >= total) return;
    int l = idx / 16384;
    int r = idx - l * 16384;
    int m = r >> 13;               // 0 = W1, 1 = W2
    int rr = r & 8191;
    int kp = rr >> 7;              // 0..63
    int n = rr & 127;
    const float* W = (m ? W2 : W1) + (size_t)l * Dq * Dq;
    float x0 = W[(2 * kp) * 128 + n];
    float x1 = W[(2 * kp + 1) * 128 + n];
    __nv_bfloat16 b0 = __float2bfloat16_rn(x0);
    __nv_bfloat16 b1 = __float2bfloat16_rn(x1);
    uint32_t hi = ((uint32_t)__bfloat16_as_ushort(b1) << 16)
                |  (uint32_t)__bfloat16_as_ushort(b0);
    uint32_t lo = packbf(x0 - __bfloat162float(b0), x1 - __bfloat162float(b1));
    uint32_t* base = g_Wpack + (size_t)l * 4 * 8192;
    base[(2 * m + 0) * 8192 + n * 64 + kp] = hi;
    base[(2 * m + 1) * 8192 + n * 64 + kp] = lo;
}

// ------------------------------------------------------------------
// CSR build
// ------------------------------------------------------------------
__global__ void k_zero_deg(int N) {
    int i = blockIdx.x * blockDim.x + threadIdx.x;
    if (i < N) g_deg[i] = 0;
}

__global__ void k_hist(const int* __restrict__ dst, int E) {
    int e = blockIdx.x * blockDim.x + threadIdx.x;
    if (e < E) atomicAdd(&g_deg[dst[e]], 1);
}

__global__ void k_scan1(int N) {
    __shared__ int wtot[32];
    int tid = threadIdx.x, lane = tid & 31, wid = tid >> 5;
    int i = blockIdx.x * SCAN_BLK + tid;
    int v = (i < N) ? g_deg[i] : 0;
    int x = v;
#pragma unroll
    for (int o = 1; o < 32; o <<= 1) {
        int t = __shfl_up_sync(0xffffffffu, x, o);
        if (lane >= o) x += t;
    }
    if (lane == 31) wtot[wid] = x;
    __syncthreads();
    if (wid == 0) {
        int w = wtot[lane];
#pragma unroll
        for (int o = 1; o < 32; o <<= 1) {
            int t = __shfl_up_sync(0xffffffffu, w, o);
            if (lane >= o) w += t;
        }
        wtot[lane] = w;
    }
    __syncthreads();
    int pre = (wid > 0 ? wtot[wid - 1] : 0);
    if (i < N) g_excl[i] = pre + x - v;
    if (tid == SCAN_BLK - 1) g_btot[blockIdx.x] = pre + x;
}

__global__ void k_scan2(int nblocks) {
    int lane = threadIdx.x & 31, wid = threadIdx.x >> 5;
    __shared__ int wtot[32];
    int i = threadIdx.x;
    int v = (i < nblocks) ? g_btot[i] : 0;
    int x = v;
#pragma unroll
    for (int o = 1; o < 32; o <<= 1) {
        int t = __shfl_up_sync(0xffffffffu, x, o);
        if (lane >= o) x += t;
    }
    if (lane == 31) wtot[wid] = x;
    __syncthreads();
    if (wid == 0) {
        int w = (lane < 2) ? wtot[lane] : 0;
#pragma unroll
        for (int o = 1; o < 32; o <<= 1) {
            int t = __shfl_up_sync(0xffffffffu, w, o);
            if (lane >= o) w += t;
        }
        wtot[lane] = w;
    }
    __syncthreads();
    int pre = (wid > 0 ? wtot[wid - 1] : 0);
    if (i <= nblocks) g_boff[i] = pre + x - v;
    if (i == nblocks) g_boff[i] = pre + x - v;
}

__global__ void k_scan3(int N, int nblocks) {
    int i = blockIdx.x * SCAN_BLK + threadIdx.x;
    if (i < N) {
        int r = g_excl[i] + g_boff[blockIdx.x];
        g_rowptr[i] = r;
        g_cursor[i] = r;
    }
    if (i == 0) g_rowptr[N] = g_boff[nblocks];
}

__global__ void k_scatter(const int* __restrict__ src, const int* __restrict__ dst,
                          const float* __restrict__ dval, int E) {
    int e = blockIdx.x * blockDim.x + threadIdx.x;
    if (e < E) {
        int p = atomicAdd(&g_cursor[dst[e]], 1);
        g_edge[p] = make_uint2((uint32_t)src[e], __float_as_uint(dval[e]));
    }
}

// ------------------------------------------------------------------
// Tensor-core GEMM, mma.sync m16n8k16 bf16 3-term split.
// Tile: M=128 x N=64 (blockIdx.x&1 = column half), K chunked at 64.
// 72 KB smem -> 2+ CTAs/SM so staging overlaps MMA across CTAs.
// ------------------------------------------------------------------
#define SPC 36                          // row stride in u32 (32 k-pairs + 4 pad)
#define A_TILE_U32 4608                 // 128 * 36
#define B_TILE_U32 2304                 // 64 * 36
#define DYN_SMEM ((2 * A_TILE_U32 + 4 * B_TILE_U32) * 4)   // 73728 bytes

__global__ __launch_bounds__(256, 2)
void k_gemm_mma(const float* __restrict__ h,
                const uint32_t* __restrict__ wpack,
                const float* __restrict__ Wal,
                int N) {
    extern __shared__ uint32_t dsu[];
    __shared__ float s_wa[256];

    uint32_t* A_hi = dsu;
    uint32_t* A_lo = dsu + A_TILE_U32;
    uint32_t* Bb   = dsu + 2 * A_TILE_U32;   // 4 tiles: B1h,B1l,B2h,B2l

    int tid = threadIdx.x, wid = tid >> 5, lane = tid & 31;
    int g = lane >> 2, tg = lane & 3;
    int rb = (blockIdx.x >> 1) * 128;
    int nh = blockIdx.x & 1;                 // column half: cols [nh*64, nh*64+64)

    s_wa[tid] = Wal[tid];

    float acc1[8][4], acc2[8][4];
#pragma unroll
    for (int nt = 0; nt < 8; ++nt)
#pragma unroll
        for (int c = 0; c < 4; ++c) { acc1[nt][c] = 0.f; acc2[nt][c] = 0.f; }

    const float4* h4 = (const float4*)h;
    const uint4* wp4 = (const uint4*)wpack;
    int arow0 = wid * 16 + g;

    for (int kc = 0; kc < 2; ++kc) {
        __syncthreads();   // smem reuse guard
        // ---- stage A chunk: 128 rows x 64 k-cols, bf16 hi/lo k-pairs ----
#pragma unroll
        for (int i = 0; i < 8; ++i) {
            int idx = tid + i * 256;            // 0..2047
            int row = idx >> 4, q = idx & 15;   // q: float4 index in 64-col chunk
            int grow = rb + row;
            float4 v = make_float4(0.f, 0.f, 0.f, 0.f);
            if (grow < N) v = h4[grow * 32 + kc * 16 + q];
            __nv_bfloat16 bx = __float2bfloat16_rn(v.x);
            __nv_bfloat16 by = __float2bfloat16_rn(v.y);
            __nv_bfloat16 bz = __float2bfloat16_rn(v.z);
            __nv_bfloat16 bw = __float2bfloat16_rn(v.w);
            uint32_t hi0 = ((uint32_t)__bfloat16_as_ushort(by) << 16)
                         |  (uint32_t)__bfloat16_as_ushort(bx);
            uint32_t hi1 = ((uint32_t)__bfloat16_as_ushort(bw) << 16)
                         |  (uint32_t)__bfloat16_as_ushort(bz);
            uint32_t lo0 = packbf(v.x - __bfloat162float(bx),
                                  v.y - __bfloat162float(by));
            uint32_t lo1 = packbf(v.z - __bfloat162float(bz),
                                  v.w - __bfloat162float(bw));
            *(uint2*)(A_hi + row * SPC + q * 2) = make_uint2(hi0, hi1);
            *(uint2*)(A_lo + row * SPC + q * 2) = make_uint2(lo0, lo1);
        }
        // ---- stage B chunk: 4 tiles x 64 n-rows x 8 uint4 (copy) ----
#pragma unroll
        for (int i = 0; i < 8; ++i) {
            int idx = tid + i * 256;              // 0..2047
            int t = idx >> 9;                     // tile 0..3
            int r = idx & 511;
            int n = r >> 3, j = r & 7;            // n: 0..63, j: uint4 in chunk
            uint4 v = wp4[t * 2048 + (nh * 64 + n) * 16 + kc * 8 + j];
            *(uint4*)(Bb + t * B_TILE_U32 + n * SPC + j * 4) = v;
        }
        __syncthreads();

        // ---- mma mainloop: 4 k16-steps per chunk ----
        uint32_t* B1h = Bb;
        uint32_t* B1l = Bb + B_TILE_U32;
        uint32_t* B2h = Bb + 2 * B_TILE_U32;
        uint32_t* B2l = Bb + 3 * B_TILE_U32;
        for (int kk = 0; kk < 4; ++kk) {
            int kp = kk * 8 + tg;
            uint32_t aH[4], aL[4];
            aH[0] = A_hi[arow0 * SPC + kp];
            aH[1] = A_hi[(arow0 + 8) * SPC + kp];
            aH[2] = A_hi[arow0 * SPC + kp + 4];
            aH[3] = A_hi[(arow0 + 8) * SPC + kp + 4];
            aL[0] = A_lo[arow0 * SPC + kp];
            aL[1] = A_lo[(arow0 + 8) * SPC + kp];
            aL[2] = A_lo[arow0 * SPC + kp + 4];
            aL[3] = A_lo[(arow0 + 8) * SPC + kp + 4];
            int rbase = g * SPC + kp;
#pragma unroll
            for (int nt = 0; nt < 8; ++nt) {
                int o = rbase + nt * 8 * SPC;
                uint32_t b1h0 = B1h[o], b1h1 = B1h[o + 4];
                uint32_t b1l0 = B1l[o], b1l1 = B1l[o + 4];
                mma16(acc1[nt], aH, b1h0, b1h1);
                mma16(acc1[nt], aL, b1h0, b1h1);
                mma16(acc1[nt], aH, b1l0, b1l1);
                uint32_t b2h0 = B2h[o], b2h1 = B2h[o + 4];
                uint32_t b2l0 = B2l[o], b2l1 = B2l[o + 4];
                mma16(acc2[nt], aH, b2h0, b2h1);
                mma16(acc2[nt], aL, b2h0, b2h1);
                mma16(acc2[nt], aH, b2l0, b2l1);
            }
        }
    }

    // ---- attention scalar PARTIALS over this column half ----
    {
        float p0r0 = 0.f, p1r0 = 0.f, p0r1 = 0.f, p1r1 = 0.f;
#pragma unroll
        for (int nt = 0; nt < 8; ++nt) {
            int c = nh * 64 + nt * 8 + tg * 2;
            float w0a = s_wa[c], w0b = s_wa[c + 1];
            float w1a = s_wa[128 + c], w1b = s_wa[128 + c + 1];
            p0r0 += acc1[nt][0] * w0a + acc1[nt][1] * w0b;
            p1r0 += acc1[nt][0] * w1a + acc1[nt][1] * w1b;
            p0r1 += acc1[nt][2] * w0a + acc1[nt][3] * w0b;
            p1r1 += acc1[nt][2] * w1a + acc1[nt][3] * w1b;
        }
#pragma unroll
        for (int o = 1; o <= 2; o <<= 1) {
            p0r0 += __shfl_xor_sync(0xffffffffu, p0r0, o);
            p1r0 += __shfl_xor_sync(0xffffffffu, p1r0, o);
            p0r1 += __shfl_xor_sync(0xffffffffu, p0r1, o);
            p1r1 += __shfl_xor_sync(0xffffffffu, p1r1, o);
        }
        if (tg == 0) {
            int rw = rb + wid * 16 + g;
            float* asf = (float*)g_as2;
            float* adf = (float*)g_ad2;
            if (rw < N)     { asf[rw * 2 + nh]       = p0r0; adf[rw * 2 + nh]       = p1r0; }
            if (rw + 8 < N) { asf[(rw + 8) * 2 + nh] = p0r1; adf[(rw + 8) * 2 + nh] = p1r1; }
        }
    }

    // ---- epilogue via smem roundtrip (buf overlays B region) ----
    float* buf = (float*)Bb;                       // [128][68] floats
    // z: packed half2 (this half: 8 uint4 per row)
    {
        __syncthreads();
        int rw0 = wid * 16 + g;
#pragma unroll
        for (int nt = 0; nt < 8; ++nt) {
            int c = nt * 8 + tg * 2;
            *(float2*)(buf + rw0 * 68 + c)       = make_float2(acc1[nt][0], acc1[nt][1]);
            *(float2*)(buf + (rw0 + 8) * 68 + c) = make_float2(acc1[nt][2], acc1[nt][3]);
        }
        __syncthreads();
#pragma unroll
        for (int i = 0; i < 4; ++i) {
            int idx = tid + i * 256;              // 0..1023
            int row = idx >> 3, q = idx & 7;      // q: uint4 within the half
            int grow = rb + row;
            if (grow < N) {
                const float* p = buf + row * 68 + q * 8;
                __half2 a = __floats2half2_rn(p[0], p[1]);
                __half2 b = __floats2half2_rn(p[2], p[3]);
                __half2 c2 = __floats2half2_rn(p[4], p[5]);
                __half2 d = __floats2half2_rn(p[6], p[7]);
                uint4 v;
                v.x = *(uint32_t*)&a; v.y = *(uint32_t*)&b;
                v.z = *(uint32_t*)&c2; v.w = *(uint32_t*)&d;
                g_zh[(size_t)grow * 16 + nh * 8 + q] = v;
            }
        }
    }
    // zi: fp32 stores (this half: 16 float4 per row)
    {
        __syncthreads();
        int rw0 = wid * 16 + g;
#pragma unroll
        for (int nt = 0; nt < 8; ++nt) {
            int c = nt * 8 + tg * 2;
            *(float2*)(buf + rw0 * 68 + c)       = make_float2(acc2[nt][0], acc2[nt][1]);
            *(float2*)(buf + (rw0 + 8) * 68 + c) = make_float2(acc2[nt][2], acc2[nt][3]);
        }
        __syncthreads();
#pragma unroll
        for (int i = 0; i < 8; ++i) {
            int idx = tid + i * 256;              // 0..2047
            int row = idx >> 4, q = idx & 15;
            int grow = rb + row;
            if (grow < N)
                ((float4*)g_zi)[grow * 32 + nh * 16 + q] =
                    *(float4*)(buf + row * 68 + q * 4);
        }
    }
}

// ------------------------------------------------------------------
// Segment softmax + weighted aggregation + residual relu (warp per node).
// Attention scalars are 2-component partial sums (one per column half).
// ------------------------------------------------------------------
__global__ void k_aggregate(const float* __restrict__ W0l,
                            const float* __restrict__ Wal,
                            float* __restrict__ out, int N) {
    int n = (blockIdx.x * blockDim.x + threadIdx.x) >> 5;
    int lane = threadIdx.x & 31;
    if (n >= N) return;

    int beg = g_rowptr[n], end = g_rowptr[n + 1];
    float coef = W0l[0] * Wal[2 * Dq];
    float2 adp = g_ad2[n];
    float ad = adp.x + adp.y;

    float ssum = 0.f;
    float4 accA = make_float4(0.f, 0.f, 0.f, 0.f);
    float4 accB = make_float4(0.f, 0.f, 0.f, 0.f);
    const uint2* zh = (const uint2*)g_zh;     // 32 uint2 (8B) per row

    for (int b = beg; b < end; b += 32) {
        int cnt = min(32, end - b);
        int s = 0;
        float ex = 0.f;
        if (lane < cnt) {
            uint2 ed = g_edge[b + lane];
            s = (int)ed.x;
            float2 ap = g_as2[s];
            float x = ap.x + ap.y + ad + __uint_as_float(ed.y) * coef;
            float e = x > 0.f ? x : 0.01f * x;
            ex = __expf(e);
        }
        float ps = ex;
#pragma unroll
        for (int o = 16; o; o >>= 1) ps += __shfl_xor_sync(0xffffffffu, ps, o);
        ssum += ps;
        int j = 0;
        for (; j + 2 <= cnt; j += 2) {
            int   s0 = __shfl_sync(0xffffffffu, s, j);
            float e0 = __shfl_sync(0xffffffffu, ex, j);
            int   s1 = __shfl_sync(0xffffffffu, s, j + 1);
            float e1 = __shfl_sync(0xffffffffu, ex, j + 1);
            uint2 r0 = zh[(size_t)s0 * 32 + lane];
            uint2 r1 = zh[(size_t)s1 * 32 + lane];
            float2 f0a = __half22float2(*reinterpret_cast<__half2*>(&r0.x));
            float2 f0b = __half22float2(*reinterpret_cast<__half2*>(&r0.y));
            float2 f1a = __half22float2(*reinterpret_cast<__half2*>(&r1.x));
            float2 f1b = __half22float2(*reinterpret_cast<__half2*>(&r1.y));
            accA.x += e0 * f0a.x; accA.y += e0 * f0a.y;
            accA.z += e0 * f0b.x; accA.w += e0 * f0b.y;
            accB.x += e1 * f1a.x; accB.y += e1 * f1a.y;
            accB.z += e1 * f1b.x; accB.w += e1 * f1b.y;
        }
        if (j < cnt) {
            int   s0 = __shfl_sync(0xffffffffu, s, j);
            float e0 = __shfl_sync(0xffffffffu, ex, j);
            uint2 r0 = zh[(size_t)s0 * 32 + lane];
            float2 f0a = __half22float2(*reinterpret_cast<__half2*>(&r0.x));
            float2 f0b = __half22float2(*reinterpret_cast<__half2*>(&r0.y));
            accA.x += e0 * f0a.x; accA.y += e0 * f0a.y;
            accA.z += e0 * f0b.x; accA.w += e0 * f0b.y;
        }
    }
    float inv = (end > beg) ? 1.f / ssum : 0.f;

    const float4* zi4 = (const float4*)g_zi;
    float4 zi = zi4[n * 32 + lane];
    float4 o;
    o.x = fmaxf(zi.x + (accA.x + accB.x) * inv, 0.f);
    o.y = fmaxf(zi.y + (accA.y + accB.y) * inv, 0.f);
    o.z = fmaxf(zi.z + (accA.z + accB.z) * inv, 0.f);
    o.w = fmaxf(zi.w + (accA.w + accB.w) * inv, 0.f);
    ((float4*)out)[n * 32 + lane] = o;
}

// ------------------------------------------------------------------
extern "C" void kernel_launch(void* const* d_in, const int* in_sizes, int n_in,
                              void* d_out, int out_size) {
    const float* attr = (const float*)d_in[0];
    const float* dval = (const float*)d_in[1];
    const int*   src  = (const int*)d_in[2];
    const int*   dst  = (const int*)d_in[3];
    const float* W0   = (const float*)d_in[4];
    const float* W1   = (const float*)d_in[5];
    const float* W2   = (const float*)d_in[6];
    const float* Wa   = (const float*)d_in[7];

    int N = in_sizes[0] / Dq;
    int E = in_sizes[2];
    int L = in_sizes[4];

    // ---- lazy-once host resources (no per-call create -> no leak delta) ----
    static cudaStream_t s2 = nullptr;
    static cudaEvent_t evFork, evCsr;
    static bool inited = false;
    if (!inited) {
        cudaStreamCreateWithFlags(&s2, cudaStreamNonBlocking);
        cudaEventCreateWithFlags(&evFork, cudaEventDisableTiming);
        cudaEventCreateWithFlags(&evCsr, cudaEventDisableTiming);
        cudaFuncSetAttribute(k_gemm_mma,
                             cudaFuncAttributeMaxDynamicSharedMemorySize,
                             DYN_SMEM);
        inited = true;
    }

    void *pA = nullptr, *pB = nullptr, *pW = nullptr;
    cudaGetSymbolAddress(&pA, g_hA);
    cudaGetSymbolAddress(&pB, g_hB);
    cudaGetSymbolAddress(&pW, g_Wpack);

    int scanBlocks = (N + SCAN_BLK - 1) / SCAN_BLK;
    int gemmBlocks = ((N + 127) / 128) * 2;   // x2 column halves
    int nodeWarpBlocks = (N * 32 + 255) / 256;

    // ---- fork: CSR build on s2 (overlaps packW + layer-0 GEMM on s0) ----
    cudaEventRecord(evFork, 0);
    cudaStreamWaitEvent(s2, evFork, 0);
    k_zero_deg<<<(N + 255) / 256, 256, 0, s2>>>(N);
    k_hist<<<(E + 255) / 256, 256, 0, s2>>>(dst, E);
    k_scan1<<<scanBlocks, SCAN_BLK, 0, s2>>>(N);
    k_scan2<<<1, 64, 0, s2>>>(scanBlocks);
    k_scan3<<<scanBlocks, SCAN_BLK, 0, s2>>>(N, scanBlocks);
    k_scatter<<<(E + 255) / 256, 256, 0, s2>>>(src, dst, dval, E);
    cudaEventRecord(evCsr, s2);

    // ---- s0: W pack + layer-0 GEMM overlap the CSR build ----
    k_packW<<<(L * 16384 + 255) / 256, 256>>>(W1, W2, L);

    const float* hin = attr;
    for (int l = 0; l < L; ++l) {
        float* hout = (l == L - 1) ? (float*)d_out
                                   : ((l & 1) ? (float*)pB : (float*)pA);
        k_gemm_mma<<<gemmBlocks, 256, DYN_SMEM>>>(
            hin, (const uint32_t*)pW + (size_t)l * 4 * 8192,
            Wa + (size_t)l * (2 * Dq + 1), N);
        if (l == 0) cudaStreamWaitEvent(0, evCsr, 0);
        k_aggregate<<<nodeWarpBlocks, 256>>>(W0 + l,
                                             Wa + (size_t)l * (2 * Dq + 1),
                                             hout, N);
        hin = hout;
    }
}